// round 11
// baseline (speedup 1.0000x reference)
#include <cuda_runtime.h>
#include <cstdint>

// GeneWiseDecoder: out[b,g] = gelu(gelu(x@W1[g]+b1) @ W2[g] + b2) @ W3[g] + b3
// B=128, LATENT=128, HID=512, GENES=1000, fp32.
// R7 structure (best so far): 2000 CTAs (gene x 64-row half), 512 threads,
// warp tile 16x64 (4 m-warps x 4 n-warps), two 256-wide N passes, K=32 chunks,
// double-buffered W with register prefetch, 1 __syncthreads per chunk.
// NEW: pair-interleaved SMEM layouts so every mma fragment is one LDS.64:
//   shW2[c][j] = (W[k][c], W[k+4][c]),  j = (k>>3)*4 + (k&3),  pitch 20 float2
//   shH2[r][j] = (h1[r][k], h1[r][k+4]), same j map over k=0..511, pitch 260 float2

static constexpr int GENES = 1000;
static constexpr int HID   = 512;
static constexpr int LAT   = 128;

static constexpr int PJW = 20;                     // W buf pitch (float2/col), 20%16==4 -> conflict-free
static constexpr int PJH = 260;                    // h1 pitch (float2/row), 260%16==4
static constexpr int WCHUNK_F = 256 * PJW * 2;     // 10240 floats per W buffer

static constexpr int OFF_H  = 0;                   // 64*260 float2 = 33280 floats
static constexpr int OFF_W  = 64 * PJH * 2;        // 33280; 2 buffers = 20480 floats
static constexpr int OFF_B1 = OFF_W + 2 * WCHUNK_F;// 53760
static constexpr int OFF_B2 = OFF_B1 + 512;        // 54272
static constexpr int OFF_W3 = OFF_B2 + 512;        // 54784
static constexpr int OFF_O  = OFF_W3 + 512;        // 55296
static constexpr int SMEM_FLOATS = OFF_O + 64;     // 55360
static constexpr int SMEM_BYTES  = SMEM_FLOATS * 4;// 221440 B (< 227 KB)

__device__ __forceinline__ float to_tf32(float v) {
    uint32_t u;
    asm("cvt.rna.tf32.f32 %0, %1;" : "=r"(u) : "f"(v));
    return __uint_as_float(u);
}

__device__ __forceinline__ uint32_t ld_tf32(const float* __restrict__ p) {
    uint32_t u;
    asm("cvt.rna.tf32.f32 %0, %1;" : "=r"(u) : "f"(*p));
    return u;
}

__device__ __forceinline__ float gelu_exact(float v) {
    return v * normcdff(v);   // jax.nn.gelu(approximate=False)
}

__device__ __forceinline__ void mma_tf32(float d[4], const uint32_t a[4],
                                         uint32_t b0, uint32_t b1) {
    asm volatile(
        "mma.sync.aligned.m16n8k8.row.col.f32.tf32.tf32.f32 "
        "{%0,%1,%2,%3},{%4,%5,%6,%7},{%8,%9},{%0,%1,%2,%3};"
        : "+f"(d[0]), "+f"(d[1]), "+f"(d[2]), "+f"(d[3])
        : "r"(a[0]), "r"(a[1]), "r"(a[2]), "r"(a[3]), "r"(b0), "r"(b1));
}

// ---- W tile staging: 32(K) x 256(N), task-mapped so k/k+4 land in one thread.
// task t (0..1023, 2 per thread): j = t&15, cq = t>>4 (col quad 0..63)
//   k_lo = (j>>2)*8 + (j&3); loads rows k0+k_lo and k0+k_lo+4, cols n0+4cq..+3
__device__ __forceinline__ void load_tileW(float4 pre[4], const float* __restrict__ gB,
                                           int k0, int n0, int tid) {
#pragma unroll
    for (int it = 0; it < 2; ++it) {
        int t  = tid + it * 512;
        int j  = t & 15;
        int cq = t >> 4;
        int k_lo = ((j >> 2) << 3) + (j & 3);
        const float* p = gB + (size_t)(k0 + k_lo) * 512 + n0 + 4 * cq;
        pre[it * 2 + 0] = *reinterpret_cast<const float4*>(p);
        pre[it * 2 + 1] = *reinterpret_cast<const float4*>(p + 4 * 512);
    }
}

// Store to pair-interleaved W buffer with RNA tf32 rounding. Conflict-free STS.64.
__device__ __forceinline__ void store_tileW(float* __restrict__ shW, const float4 pre[4],
                                            int tid) {
    float2* b2 = reinterpret_cast<float2*>(shW);
#pragma unroll
    for (int it = 0; it < 2; ++it) {
        int t  = tid + it * 512;
        int j  = t & 15;
        int cq = t >> 4;
        const float4 lo = pre[it * 2 + 0];
        const float4 hi = pre[it * 2 + 1];
        int c0 = 4 * cq;
        b2[(c0 + 0) * PJW + j] = make_float2(to_tf32(lo.x), to_tf32(hi.x));
        b2[(c0 + 1) * PJW + j] = make_float2(to_tf32(lo.y), to_tf32(hi.y));
        b2[(c0 + 2) * PJW + j] = make_float2(to_tf32(lo.z), to_tf32(hi.z));
        b2[(c0 + 3) * PJW + j] = make_float2(to_tf32(lo.w), to_tf32(hi.w));
    }
}

// One K=32 chunk, A from pair-interleaved shH. Warp tile 16x64 (8 nf).
__device__ __forceinline__ void mma_chunk_sh(float acc[8][4],
                                             const float2* __restrict__ A2, int kBase,
                                             const float2* __restrict__ B2,
                                             int wm, int wn, int grp, int qt) {
    const int r0  = wm * 16 + grp;
    const int jA0 = (kBase >> 3) * 4 + qt;
#pragma unroll
    for (int k8 = 0; k8 < 4; ++k8) {
        float2 x0 = A2[r0 * PJH + jA0 + k8 * 4];        // (A[r][k],   A[r][k+4])
        float2 x1 = A2[(r0 + 8) * PJH + jA0 + k8 * 4];  // (A[r+8][k], A[r+8][k+4])
        uint32_t a[4] = { __float_as_uint(x0.x), __float_as_uint(x1.x),
                          __float_as_uint(x0.y), __float_as_uint(x1.y) };
        const int jb = k8 * 4 + qt;
#pragma unroll
        for (int nf = 0; nf < 8; ++nf) {
            int cb = wn * 64 + nf * 8 + grp;
            float2 b = B2[cb * PJW + jb];
            mma_tf32(acc[nf], a, __float_as_uint(b.x), __float_as_uint(b.y));
        }
    }
}

// One K=32 chunk, A straight from global x (fp32 -> tf32 at load; L1/L2-hot).
__device__ __forceinline__ void mma_chunk_gx(float acc[8][4],
                                             const float* __restrict__ xg, int kBase,
                                             const float2* __restrict__ B2,
                                             int wm, int wn, int grp, int qt) {
    const int r0 = wm * 16 + grp;
#pragma unroll
    for (int k8 = 0; k8 < 4; ++k8) {
        const int cA = kBase + k8 * 8 + qt;
        uint32_t a[4];
        a[0] = ld_tf32(xg + (size_t)r0 * LAT + cA);
        a[1] = ld_tf32(xg + (size_t)(r0 + 8) * LAT + cA);
        a[2] = ld_tf32(xg + (size_t)r0 * LAT + cA + 4);
        a[3] = ld_tf32(xg + (size_t)(r0 + 8) * LAT + cA + 4);
        const int jb = k8 * 4 + qt;
#pragma unroll
        for (int nf = 0; nf < 8; ++nf) {
            int cb = wn * 64 + nf * 8 + grp;
            float2 b = B2[cb * PJW + jb];
            mma_tf32(acc[nf], a, __float_as_uint(b.x), __float_as_uint(b.y));
        }
    }
}

__global__ void __launch_bounds__(512, 1)
gene_mlp_kernel(const float* __restrict__ x,
                const float* __restrict__ W1, const float* __restrict__ b1,
                const float* __restrict__ W2, const float* __restrict__ b2,
                const float* __restrict__ W3, const float* __restrict__ b3,
                float* __restrict__ out) {
    extern __shared__ float sm[];
    float*  shH  = sm + OFF_H;                            // pair-interleaved h1
    float*  shW  = sm + OFF_W;                            // 2 pair-interleaved W buffers
    float*  shB1 = sm + OFF_B1;
    float*  shB2 = sm + OFF_B2;
    float*  shW3 = sm + OFF_W3;
    float*  shO  = sm + OFF_O;
    const float2* H2 = reinterpret_cast<const float2*>(shH);

    const int g       = blockIdx.x >> 1;
    const int rowbase = (blockIdx.x & 1) * 64;
    const int tid  = threadIdx.x;
    const int lane = tid & 31;
    const int warp = tid >> 5;       // 0..15
    const int wm = warp & 3;         // 4 m-warps (16 rows each)
    const int wn = warp >> 2;        // 4 n-warps (64 cols each, within 256-wide pass)
    const int grp = lane >> 2;
    const int qt  = lane & 3;

    // ---- stage biases / W3, zero output accumulator ----
    shB1[tid] = b1[(size_t)g * HID + tid];
    shB2[tid] = b2[(size_t)g * HID + tid];
    shW3[tid] = W3[(size_t)g * HID + tid];
    if (tid < 64) shO[tid] = 0.0f;

    const float* xg = x + (size_t)rowbase * LAT;

    // ================= Phase 1: h1 = gelu(x @ W1 + b1) -> shH (paired tf32) =====
    const float* W1g = W1 + (size_t)g * LAT * HID;
#pragma unroll 1
    for (int n1t = 0; n1t < 2; ++n1t) {
        const int n0 = n1t * 256;
        float acc[8][4];
#pragma unroll
        for (int nf = 0; nf < 8; ++nf)
#pragma unroll
            for (int i = 0; i < 4; ++i) acc[nf][i] = 0.0f;

        float4 pre[4];
        load_tileW(pre, W1g, 0, n0, tid);
        store_tileW(shW, pre, tid);                 // chunk 0 -> buf 0
        load_tileW(pre, W1g, 32, n0, tid);          // chunk 1 -> regs
        __syncthreads();
#pragma unroll 1
        for (int kc = 0; kc < 4; ++kc) {
            if (kc + 1 < 4) store_tileW(shW + ((kc + 1) & 1) * WCHUNK_F, pre, tid);
            if (kc + 2 < 4) load_tileW(pre, W1g, (kc + 2) * 32, n0, tid);
            mma_chunk_gx(acc, xg, kc * 32,
                         reinterpret_cast<const float2*>(shW + (kc & 1) * WCHUNK_F),
                         wm, wn, grp, qt);
            __syncthreads();
        }
        // epilogue: bias + gelu + pair-interleaved tf32 store into shH
#pragma unroll
        for (int nf = 0; nf < 8; ++nf)
#pragma unroll
            for (int i = 0; i < 4; ++i) {
                int row = wm * 16 + (i >> 1) * 8 + grp;
                int col = n0 + wn * 64 + nf * 8 + 2 * qt + (i & 1);
                int cm8 = col & 7;
                int word = row * (PJH * 2) + (col >> 3) * 8 + (cm8 & 3) * 2 + (cm8 >> 2);
                float v = acc[nf][i] + shB1[col];
                shH[word] = to_tf32(gelu_exact(v));
            }
    }

    // ================= Phase 2: h2 = gelu(h1 @ W2 + b2); out += h2 . W3 =========
    const float* W2g = W2 + (size_t)g * HID * HID;
#pragma unroll 1
    for (int n2t = 0; n2t < 2; ++n2t) {
        const int n0 = n2t * 256;
        float acc[8][4];
#pragma unroll
        for (int nf = 0; nf < 8; ++nf)
#pragma unroll
            for (int i = 0; i < 4; ++i) acc[nf][i] = 0.0f;

        float4 pre[4];
        load_tileW(pre, W2g, 0, n0, tid);
        store_tileW(shW, pre, tid);
        load_tileW(pre, W2g, 32, n0, tid);
        __syncthreads();                            // also orders phase-1 shH writes
#pragma unroll 1
        for (int kc = 0; kc < 16; ++kc) {
            if (kc + 1 < 16) store_tileW(shW + ((kc + 1) & 1) * WCHUNK_F, pre, tid);
            if (kc + 2 < 16) load_tileW(pre, W2g, (kc + 2) * 32, n0, tid);
            mma_chunk_sh(acc, H2, kc * 32,
                         reinterpret_cast<const float2*>(shW + (kc & 1) * WCHUNK_F),
                         wm, wn, grp, qt);
            __syncthreads();
        }
        // epilogue: bias + gelu + fused dot with W3 (fp32)
        float part[2] = {0.f, 0.f};
#pragma unroll
        for (int nf = 0; nf < 8; ++nf)
#pragma unroll
            for (int i = 0; i < 4; ++i) {
                int col = n0 + wn * 64 + nf * 8 + 2 * qt + (i & 1);
                float v = gelu_exact(acc[nf][i] + shB2[col]);
                part[i >> 1] += v * shW3[col];
            }
#pragma unroll
        for (int r = 0; r < 2; ++r) {
            part[r] += __shfl_xor_sync(0xffffffffu, part[r], 1);
            part[r] += __shfl_xor_sync(0xffffffffu, part[r], 2);
        }
        if (qt == 0) {
            atomicAdd(&shO[wm * 16 + grp],     part[0]);
            atomicAdd(&shO[wm * 16 + 8 + grp], part[1]);
        }
    }

    __syncthreads();
    if (tid < 64) {
        out[(size_t)(rowbase + tid) * GENES + g] = shO[tid] + b3[g];
    }
}

extern "C" void kernel_launch(void* const* d_in, const int* in_sizes, int n_in,
                              void* d_out, int out_size) {
    const float* x  = (const float*)d_in[0];
    const float* W1 = (const float*)d_in[1];
    const float* b1 = (const float*)d_in[2];
    const float* W2 = (const float*)d_in[3];
    const float* b2 = (const float*)d_in[4];
    const float* W3 = (const float*)d_in[5];
    const float* b3 = (const float*)d_in[6];
    float* out = (float*)d_out;

    cudaFuncSetAttribute(gene_mlp_kernel,
                         cudaFuncAttributeMaxDynamicSharedMemorySize, SMEM_BYTES);
    gene_mlp_kernel<<<2 * GENES, 512, SMEM_BYTES>>>(x, W1, b1, W2, b2, W3, b3, out);
}